// round 10
// baseline (speedup 1.0000x reference)
#include <cuda_runtime.h>
#include <stdint.h>

#define NB 4096
#define ND 128
#define NCLS 80
#define EN 4
#define THREADS 128

__device__ float g_partials[2 * NB];
__device__ __align__(16) unsigned char g_cls8[NB];

// ---------------------------------------------------------------------------
// Threefry-2x32, 20 rounds (exact jax threefry2x32) — single-stream version,
// used once per block to derive the per-direction key.
// ---------------------------------------------------------------------------
__device__ __forceinline__ void tf2x32(uint32_t k0, uint32_t k1,
                                       uint32_t x0, uint32_t x1,
                                       uint32_t& o0, uint32_t& o1) {
    uint32_t ks2 = k0 ^ k1 ^ 0x1BD11BDAu;
    x0 += k0; x1 += k1;
#define TF_R(r) { x0 += x1; x1 = __funnelshift_l(x1, x1, (r)); x1 ^= x0; }
#define TF_R4(a,b,c,d) TF_R(a) TF_R(b) TF_R(c) TF_R(d)
    TF_R4(13,15,26,6)   x0 += k1;  x1 += ks2 + 1u;
    TF_R4(17,29,16,24)  x0 += ks2; x1 += k0  + 2u;
    TF_R4(13,15,26,6)   x0 += k0;  x1 += k1  + 3u;
    TF_R4(17,29,16,24)  x0 += k1;  x1 += ks2 + 4u;
    TF_R4(13,15,26,6)   x0 += ks2; x1 += k0  + 5u;
#undef TF_R4
#undef TF_R
    o0 = x0; o1 = x1;
}

// 64-bit descending-sorted insert (merge phase only; rare)
#define INS4(kk)                                                              \
    { unsigned long long k_ = (kk);                                           \
      if (k_ > t3) {                                                          \
        if (k_ > t2) {                                                        \
          t3 = t2;                                                            \
          if (k_ > t1) { t2 = t1;                                             \
            if (k_ > t0) { t1 = t0; t0 = k_; } else t1 = k_;                  \
          } else t2 = k_;                                                     \
        } else t3 = k_;                                                       \
      }                                                                       \
    }

// Branchless 32-bit sorted-insert: 7 IMNMX
#define INS4_32(kk)                                                           \
    { uint32_t k_ = (kk);                                                     \
      uint32_t l0 = umin(u0, k_); u0 = umax(u0, k_);                          \
      uint32_t l1 = umin(u1, l0); u1 = umax(u1, l0);                          \
      uint32_t l2 = umin(u2, l1); u2 = umax(u2, l1);                          \
      u3 = umax(u3, l2);                                                      \
    }

// ---------------------------------------------------------------------------
// Kernel 1: one-hot labels -> class id (uint8). One warp per row.
// ---------------------------------------------------------------------------
__global__ __launch_bounds__(256) void cls_kernel(const float* __restrict__ labels) {
    int gwarp = (blockIdx.x * 256 + threadIdx.x) >> 5;   // 0..NB-1
    int lane  = threadIdx.x & 31;
    if (gwarp < NB) {
        const float* L = labels + (size_t)gwarp * NCLS;
        int c = 0;
        #pragma unroll
        for (int j = lane; j < NCLS; j += 32)
            if (L[j] > 0.5f) c = j;
        c = __reduce_max_sync(0xffffffffu, c);
        if (lane == 0) g_cls8[gwarp] = (unsigned char)c;
    }
}

// ---------------------------------------------------------------------------
// Kernel 2: per (direction,row) threefry top-4 sampling + triplet terms.
// ---------------------------------------------------------------------------
__global__ __launch_bounds__(THREADS) void triplet_kernel(
    const float* __restrict__ img, const float* __restrict__ txt) {

    __shared__ __align__(16) unsigned char s_cls[NB];
    __shared__ unsigned long long s_top[16];
    __shared__ int   s_idx[EN];
    __shared__ float s_dist[EN + 1];

    const int tid = threadIdx.x;
    const int bid = blockIdx.x;
    const int dir = bid >> 12;
    const int row = bid & (NB - 1);

    // stage class table (4KB) via 16B copies
    {
        const uint4* src = (const uint4*)g_cls8;
        uint4* dst = (uint4*)s_cls;
        #pragma unroll
        for (int i = tid; i < NB / 16; i += THREADS) dst[i] = src[i];
    }
    __syncthreads();

    // key(42) -> (0,42); partitionable split: ks_d = threefry((0,42),(0,dir))
    uint32_t k0, k1;
    tf2x32(0u, 42u, 0u, (uint32_t)dir, k0, k1);
    const uint32_t ks2 = k0 ^ k1 ^ 0x1BD11BDAu;
    const uint32_t kc1 = ks2 + 1u, kc2 = k0 + 2u, kc3 = k1 + 3u,
                   kc4 = ks2 + 4u, kc5 = k0 + 5u;

    const unsigned myc = s_cls[row];
    const uint32_t base = (uint32_t)row * (uint32_t)NB + (uint32_t)tid;

    // thread-local top-4, 32-bit keys: (mantissa23 << 5) | (31 - q), q = local ordinal
    uint32_t u0 = 0, u1 = 0, u2 = 0, u3 = 0;

    #pragma unroll 4
    for (int q2 = 0; q2 < 16; q2++) {
        const uint32_t cA = base + (uint32_t)(q2 * 256);
        const uint32_t cB = cA + 128u;
        // two interleaved threefry streams (x0 = 0 counter-hi)
        uint32_t a0 = k0, a1 = cA + k1;
        uint32_t b0 = k0, b1 = cB + k1;
#define R2(r) { a0 += a1; a1 = __funnelshift_l(a1,a1,(r)); a1 ^= a0;          \
                b0 += b1; b1 = __funnelshift_l(b1,b1,(r)); b1 ^= b0; }
        R2(13) R2(15) R2(26) R2(6)
        a0 += k1;  a1 += kc1;  b0 += k1;  b1 += kc1;
        R2(17) R2(29) R2(16) R2(24)
        a0 += ks2; a1 += kc2;  b0 += ks2; b1 += kc2;
        R2(13) R2(15) R2(26) R2(6)
        a0 += k0;  a1 += kc3;  b0 += k0;  b1 += kc3;
        R2(17) R2(29) R2(16) R2(24)
        a0 += k1;  a1 += kc4;  b0 += k1;  b1 += kc4;
        R2(13) R2(15) R2(26) R2(6)
        a0 += ks2; a1 += kc5;  b0 += ks2; b1 += kc5;
#undef R2
        const uint32_t bitsA = a0 ^ a1;
        const uint32_t bitsB = b0 ^ b1;

        const int jA = tid + q2 * 256;
        const unsigned cjA = s_cls[jA];
        const unsigned cjB = s_cls[jA + 128];

        uint32_t keyA = ((bitsA >> 4) & 0xFFFFFFE0u) | (uint32_t)(31 - 2 * q2);
        uint32_t keyB = ((bitsB >> 4) & 0xFFFFFFE0u) | (uint32_t)(30 - 2 * q2);
        keyA = (cjA != myc) ? keyA : 0u;
        keyB = (cjB != myc) ? keyB : 0u;
        INS4_32(keyA);
        INS4_32(keyB);
    }

    // expand local keys to 64-bit global keys: (m << 12) | (4095 - j)
    unsigned long long t0, t1, t2, t3;
    {
        const uint32_t tu = (uint32_t)tid;
        #define EXPAND(u) ( ((unsigned long long)((u) >> 5) << 12) |          \
            (unsigned long long)(4095u - (tu + ((31u - ((u) & 31u)) << 7))) )
        t0 = EXPAND(u0); t1 = EXPAND(u1); t2 = EXPAND(u2); t3 = EXPAND(u3);
        #undef EXPAND
    }

    // warp butterfly merge
    #pragma unroll
    for (int off = 16; off; off >>= 1) {
        unsigned long long p0 = __shfl_xor_sync(0xffffffffu, t0, off);
        unsigned long long p1 = __shfl_xor_sync(0xffffffffu, t1, off);
        unsigned long long p2 = __shfl_xor_sync(0xffffffffu, t2, off);
        unsigned long long p3 = __shfl_xor_sync(0xffffffffu, t3, off);
        INS4(p0); INS4(p1); INS4(p2); INS4(p3);
    }

    const int wid = tid >> 5, lane = tid & 31;
    if (lane == 0) {
        s_top[wid * 4 + 0] = t0; s_top[wid * 4 + 1] = t1;
        s_top[wid * 4 + 2] = t2; s_top[wid * 4 + 3] = t3;
    }
    __syncthreads();

    if (tid == 0) {
        t0 = s_top[0]; t1 = s_top[1]; t2 = s_top[2]; t3 = s_top[3];
        #pragma unroll
        for (int k = 4; k < 16; k++) INS4(s_top[k]);
        s_idx[0] = 4095 - (int)((uint32_t)t0 & 4095u);
        s_idx[1] = 4095 - (int)((uint32_t)t1 & 4095u);
        s_idx[2] = 4095 - (int)((uint32_t)t2 & 4095u);
        s_idx[3] = 4095 - (int)((uint32_t)t3 & 4095u);
    }
    __syncthreads();

    // distances: warp w -> negative w; warp 0 also positive. float4 loads.
    const float4* a4 = (const float4*)((dir ? txt : img) + (size_t)row * ND);
    const float*  bb = dir ? img : txt;

    {
        const float4* b4 = (const float4*)(bb + (size_t)s_idx[wid] * ND);
        float4 av = a4[lane], bv = b4[lane];
        float dx = av.x - bv.x, dy = av.y - bv.y,
              dz = av.z - bv.z, dw = av.w - bv.w;
        float s = fmaf(dx, dx, fmaf(dy, dy, fmaf(dz, dz, dw * dw)));
        #pragma unroll
        for (int off = 16; off; off >>= 1)
            s += __shfl_xor_sync(0xffffffffu, s, off);
        if (lane == 0) s_dist[wid] = sqrtf(s);
    }
    if (wid == 0) {
        const float4* b4 = (const float4*)(bb + (size_t)row * ND);
        float4 av = a4[lane], bv = b4[lane];
        float dx = av.x - bv.x, dy = av.y - bv.y,
              dz = av.z - bv.z, dw = av.w - bv.w;
        float s = fmaf(dx, dx, fmaf(dy, dy, fmaf(dz, dz, dw * dw)));
        #pragma unroll
        for (int off = 16; off; off >>= 1)
            s += __shfl_xor_sync(0xffffffffu, s, off);
        if (lane == 0) s_dist[EN] = sqrtf(s);
    }
    __syncthreads();

    if (tid == 0) {
        float pos = s_dist[EN];
        float acc = 0.0f;
        #pragma unroll
        for (int k = 0; k < EN; k++)
            acc += fmaxf(pos - s_dist[k] + 1.0f, 0.0f);
        g_partials[bid] = acc;
    }
}

// ---------------------------------------------------------------------------
// Kernel 3: deterministic reduction -> loss = sum / (NB*EN)
// ---------------------------------------------------------------------------
__global__ void reduce_kernel(float* __restrict__ out) {
    __shared__ float s[256];
    int tid = threadIdx.x;
    float v = 0.0f;
    for (int i = tid; i < 2 * NB; i += 256) v += g_partials[i];
    s[tid] = v;
    __syncthreads();
    #pragma unroll
    for (int off = 128; off; off >>= 1) {
        if (tid < off) s[tid] += s[tid + off];
        __syncthreads();
    }
    if (tid == 0) out[0] = s[0] / (float)(NB * EN);
}

// ---------------------------------------------------------------------------
extern "C" void kernel_launch(void* const* d_in, const int* in_sizes, int n_in,
                              void* d_out, int out_size) {
    (void)in_sizes; (void)n_in; (void)out_size;
    const float* img    = (const float*)d_in[0];
    const float* txt    = (const float*)d_in[1];
    const float* labels = (const float*)d_in[2];
    float* out = (float*)d_out;

    cls_kernel<<<NB / 8, 256>>>(labels);
    triplet_kernel<<<2 * NB, THREADS>>>(img, txt);
    reduce_kernel<<<1, 256>>>(out);
}

// round 15
// speedup vs baseline: 1.3727x; 1.3727x over previous
#include <cuda_runtime.h>
#include <stdint.h>

#define NB 4096
#define ND 128
#define NCLS 80
#define EN 4
#define THREADS 128

__device__ float g_partials[2 * NB];
__device__ __align__(16) unsigned char g_cls8[NB];

// ---------------------------------------------------------------------------
// Threefry-2x32, 20 rounds — exact match of jax threefry2x32
// ---------------------------------------------------------------------------
__device__ __forceinline__ void tf2x32(uint32_t k0, uint32_t k1,
                                       uint32_t x0, uint32_t x1,
                                       uint32_t& o0, uint32_t& o1) {
    uint32_t ks2 = k0 ^ k1 ^ 0x1BD11BDAu;
    x0 += k0; x1 += k1;
#define TF_R(r) { x0 += x1; x1 = __funnelshift_l(x1, x1, (r)); x1 ^= x0; }
#define TF_R4(a,b,c,d) TF_R(a) TF_R(b) TF_R(c) TF_R(d)
    TF_R4(13,15,26,6)   x0 += k1;  x1 += ks2 + 1u;
    TF_R4(17,29,16,24)  x0 += ks2; x1 += k0  + 2u;
    TF_R4(13,15,26,6)   x0 += k0;  x1 += k1  + 3u;
    TF_R4(17,29,16,24)  x0 += k1;  x1 += ks2 + 4u;
    TF_R4(13,15,26,6)   x0 += ks2; x1 += k0  + 5u;
#undef TF_R4
#undef TF_R
    o0 = x0; o1 = x1;
}

// Descending-sorted top-4 insert (branchy: compare usually fails, cheap)
#define INS4(kk)                                                              \
    { unsigned long long k_ = (kk);                                           \
      if (k_ > t3) {                                                          \
        if (k_ > t2) {                                                        \
          t3 = t2;                                                            \
          if (k_ > t1) { t2 = t1;                                             \
            if (k_ > t0) { t1 = t0; t0 = k_; } else t1 = k_;                  \
          } else t2 = k_;                                                     \
        } else t3 = k_;                                                       \
      }                                                                       \
    }

// ---------------------------------------------------------------------------
// Kernel 1: one-hot labels -> class id (uint8). One warp per row. (validated)
// ---------------------------------------------------------------------------
__global__ __launch_bounds__(256) void cls_kernel(const float* __restrict__ labels) {
    int gwarp = (blockIdx.x * 256 + threadIdx.x) >> 5;   // 0..NB-1
    int lane  = threadIdx.x & 31;
    if (gwarp < NB) {
        const float* L = labels + (size_t)gwarp * NCLS;
        int c = 0;
        #pragma unroll
        for (int j = lane; j < NCLS; j += 32)
            if (L[j] > 0.5f) c = j;
        c = __reduce_max_sync(0xffffffffu, c);
        if (lane == 0) g_cls8[gwarp] = (unsigned char)c;
    }
}

// ---------------------------------------------------------------------------
// Kernel 2: per (direction,row) threefry top-4 sampling + triplet terms.
// Mainloop structure identical to the measured-good Round-1 kernel; only the
// class table (uint8/4KB, uint4-staged) and distance loads (float4) changed.
// ---------------------------------------------------------------------------
__global__ __launch_bounds__(THREADS) void triplet_kernel(
    const float* __restrict__ img, const float* __restrict__ txt) {

    __shared__ __align__(16) unsigned char s_cls[NB];
    __shared__ unsigned long long s_top[16];
    __shared__ int   s_idx[EN];
    __shared__ float s_dist[EN + 1];

    const int tid = threadIdx.x;
    const int bid = blockIdx.x;
    const int dir = bid >> 12;
    const int row = bid & (NB - 1);

    // stage class table (4KB) via 16B copies
    {
        const uint4* src = (const uint4*)g_cls8;
        uint4* dst = (uint4*)s_cls;
        #pragma unroll
        for (int i = tid; i < NB / 16; i += THREADS) dst[i] = src[i];
    }
    __syncthreads();

    // key(42) -> (0,42); partitionable split: ks_d = threefry((0,42),(0,dir))
    uint32_t ka, kb;
    tf2x32(0u, 42u, 0u, (uint32_t)dir, ka, kb);

    const unsigned myc = s_cls[row];
    const uint32_t base = (uint32_t)row * (uint32_t)NB;

    // local top-4 (packed key: mantissa23 << 32 | (4095 - j))
    unsigned long long t0 = 0, t1 = 0, t2 = 0, t3 = 0;

    for (int j = tid; j < NB; j += THREADS) {
        if (s_cls[j] != myc) {
            uint32_t o0, o1;
            tf2x32(ka, kb, 0u, base + (uint32_t)j, o0, o1);
            uint32_t m = (o0 ^ o1) >> 9;   // 23-bit mantissa; monotone in uniform
            unsigned long long key =
                ((unsigned long long)m << 32) |
                (unsigned long long)(uint32_t)(NB - 1 - j);
            INS4(key);
        }
    }

    // warp butterfly merge of sorted-4 lists
    #pragma unroll
    for (int off = 16; off; off >>= 1) {
        unsigned long long p0 = __shfl_xor_sync(0xffffffffu, t0, off);
        unsigned long long p1 = __shfl_xor_sync(0xffffffffu, t1, off);
        unsigned long long p2 = __shfl_xor_sync(0xffffffffu, t2, off);
        unsigned long long p3 = __shfl_xor_sync(0xffffffffu, t3, off);
        INS4(p0); INS4(p1); INS4(p2); INS4(p3);
    }

    const int wid = tid >> 5, lane = tid & 31;
    if (lane == 0) {
        s_top[wid * 4 + 0] = t0; s_top[wid * 4 + 1] = t1;
        s_top[wid * 4 + 2] = t2; s_top[wid * 4 + 3] = t3;
    }
    __syncthreads();

    if (tid == 0) {
        t0 = s_top[0]; t1 = s_top[1]; t2 = s_top[2]; t3 = s_top[3];
        #pragma unroll
        for (int k = 4; k < 16; k++) INS4(s_top[k]);
        s_idx[0] = NB - 1 - (int)(uint32_t)(t0 & 0xffffffffu);
        s_idx[1] = NB - 1 - (int)(uint32_t)(t1 & 0xffffffffu);
        s_idx[2] = NB - 1 - (int)(uint32_t)(t2 & 0xffffffffu);
        s_idx[3] = NB - 1 - (int)(uint32_t)(t3 & 0xffffffffu);
    }
    __syncthreads();

    // distances: warp w -> negative w; warp 0 also positive. float4 loads.
    const float4* a4 = (const float4*)((dir ? txt : img) + (size_t)row * ND);
    const float*  bb = dir ? img : txt;

    {
        const float4* b4 = (const float4*)(bb + (size_t)s_idx[wid] * ND);
        float4 av = a4[lane], bv = b4[lane];
        float dx = av.x - bv.x, dy = av.y - bv.y,
              dz = av.z - bv.z, dw = av.w - bv.w;
        float s = fmaf(dx, dx, fmaf(dy, dy, fmaf(dz, dz, dw * dw)));
        #pragma unroll
        for (int off = 16; off; off >>= 1)
            s += __shfl_xor_sync(0xffffffffu, s, off);
        if (lane == 0) s_dist[wid] = sqrtf(s);
    }
    if (wid == 0) {
        const float4* b4 = (const float4*)(bb + (size_t)row * ND);
        float4 av = a4[lane], bv = b4[lane];
        float dx = av.x - bv.x, dy = av.y - bv.y,
              dz = av.z - bv.z, dw = av.w - bv.w;
        float s = fmaf(dx, dx, fmaf(dy, dy, fmaf(dz, dz, dw * dw)));
        #pragma unroll
        for (int off = 16; off; off >>= 1)
            s += __shfl_xor_sync(0xffffffffu, s, off);
        if (lane == 0) s_dist[EN] = sqrtf(s);
    }
    __syncthreads();

    if (tid == 0) {
        float pos = s_dist[EN];
        float acc = 0.0f;
        #pragma unroll
        for (int k = 0; k < EN; k++)
            acc += fmaxf(pos - s_dist[k] + 1.0f, 0.0f);
        g_partials[bid] = acc;
    }
}

// ---------------------------------------------------------------------------
// Kernel 3: deterministic reduction -> loss = sum / (NB*EN)
// ---------------------------------------------------------------------------
__global__ void reduce_kernel(float* __restrict__ out) {
    __shared__ float s[256];
    int tid = threadIdx.x;
    float v = 0.0f;
    for (int i = tid; i < 2 * NB; i += 256) v += g_partials[i];
    s[tid] = v;
    __syncthreads();
    #pragma unroll
    for (int off = 128; off; off >>= 1) {
        if (tid < off) s[tid] += s[tid + off];
        __syncthreads();
    }
    if (tid == 0) out[0] = s[0] / (float)(NB * EN);
}

// ---------------------------------------------------------------------------
extern "C" void kernel_launch(void* const* d_in, const int* in_sizes, int n_in,
                              void* d_out, int out_size) {
    (void)in_sizes; (void)n_in; (void)out_size;
    const float* img    = (const float*)d_in[0];
    const float* txt    = (const float*)d_in[1];
    const float* labels = (const float*)d_in[2];
    float* out = (float*)d_out;

    cls_kernel<<<NB / 8, 256>>>(labels);
    triplet_kernel<<<2 * NB, THREADS>>>(img, txt);
    reduce_kernel<<<1, 256>>>(out);
}